// round 11
// baseline (speedup 1.0000x reference)
#include <cuda_runtime.h>
#include <cstdint>
#include <cstddef>

// ---------------------------------------------------------------------------
// Problem constants
// ---------------------------------------------------------------------------
#define B_SZ   32
#define NTOK   577
#define BSTR   578                    // padded bias row stride (even -> 8B aligned)
#define HEADS  8
#define DIM_C  512
#define HD     64
#define MROWS  (B_SZ * NTOK)          // 18464
#define NN     (NTOK * NTOK)          // 332929
#define QKVW   (3 * DIM_C)            // 1536
#define LOG2E  1.4426950408889634f

// ---------------------------------------------------------------------------
// Scratch
// ---------------------------------------------------------------------------
__device__ float g_qkv[MROWS * QKVW];        // [B*N, 1536], tf32-rounded
__device__ float g_bias[HEADS * NTOK * BSTR];// [H, N, 578], pre-scaled by log2e
__device__ float g_att[MROWS * DIM_C];       // [B*N, 512], tf32-rounded
__device__ float g_xr[MROWS * DIM_C];        // x, tf32-rounded
__device__ float g_wqkv[QKVW * DIM_C];       // qkv_w, tf32-rounded
__device__ float g_wp[DIM_C * DIM_C];        // proj_w, tf32-rounded

// ---------------------------------------------------------------------------
// helpers
// ---------------------------------------------------------------------------
__device__ __forceinline__ unsigned f2tf32(float x) {
    unsigned r;
    asm("cvt.rna.tf32.f32 %0, %1;" : "=r"(r) : "f"(x));
    return r;
}

__device__ __forceinline__ void mma_tf32(float* d, const uint4& a, const uint2& b) {
    asm volatile(
        "mma.sync.aligned.m16n8k8.row.col.f32.tf32.tf32.f32 "
        "{%0,%1,%2,%3}, {%4,%5,%6,%7}, {%8,%9}, {%0,%1,%2,%3};\n"
        : "+f"(d[0]), "+f"(d[1]), "+f"(d[2]), "+f"(d[3])
        : "r"(a.x), "r"(a.y), "r"(a.z), "r"(a.w), "r"(b.x), "r"(b.y));
}

__device__ __forceinline__ void ldsm4(uint4& r, uint32_t addr) {
    asm volatile("ldmatrix.sync.aligned.m8n8.x4.shared.b16 {%0,%1,%2,%3}, [%4];"
                 : "=r"(r.x), "=r"(r.y), "=r"(r.z), "=r"(r.w) : "r"(addr));
}

__device__ __forceinline__ void cp16(uint32_t dst, const void* src, bool valid) {
    int sz = valid ? 16 : 0;
    asm volatile("cp.async.cg.shared.global [%0], [%1], 16, %2;\n"
                 :: "r"(dst), "l"(src), "r"(sz));
}

__device__ __forceinline__ void cp4(uint32_t dst, const void* src, bool valid) {
    int sz = valid ? 4 : 0;
    asm volatile("cp.async.ca.shared.global [%0], [%1], 4, %2;\n"
                 :: "r"(dst), "l"(src), "r"(sz));
}

#define CP_COMMIT() asm volatile("cp.async.commit_group;\n" ::: "memory")
#define CP_WAIT(n)  asm volatile("cp.async.wait_group %0;\n" :: "n"(n) : "memory")

// ---------------------------------------------------------------------------
// Kernel: round fp32 -> tf32 values (vectorized)
// ---------------------------------------------------------------------------
__global__ void __launch_bounds__(256) round_kernel(const float* __restrict__ src,
                                                    float* __restrict__ dst, int n4) {
    int i = blockIdx.x * 256 + threadIdx.x;
    if (i >= n4) return;
    float4 v = reinterpret_cast<const float4*>(src)[i];
    v.x = __uint_as_float(f2tf32(v.x));
    v.y = __uint_as_float(f2tf32(v.y));
    v.z = __uint_as_float(f2tf32(v.z));
    v.w = __uint_as_float(f2tf32(v.w));
    reinterpret_cast<float4*>(dst)[i] = v;
}

// ---------------------------------------------------------------------------
// Kernel: materialize relative-position bias, padded stride, log2e-scaled
// ---------------------------------------------------------------------------
__global__ void __launch_bounds__(256) bias_kernel(const float* __restrict__ table,
                                                   const int* __restrict__ rel) {
    int ij = blockIdx.x * 256 + threadIdx.x;
    if (ij >= NN) return;
    int i = ij / NTOK, j = ij - i * NTOK;
    int idx = rel[ij];
    const float* t = table + (size_t)idx * HEADS;
#pragma unroll
    for (int h = 0; h < HEADS; h++)
        g_bias[((size_t)h * NTOK + i) * BSTR + j] = t[h] * LOG2E;
}

// ---------------------------------------------------------------------------
// cp.async + ldmatrix tf32 GEMM (unchanged from R7 passing version)
// ---------------------------------------------------------------------------
template<bool CVT_OUT, bool ADD_BIAS>
__global__ void __launch_bounds__(256, 2) gemm_cp(const float* __restrict__ A,
                                                  const float* __restrict__ Bm,
                                                  const float* __restrict__ bias,
                                                  float* __restrict__ C,
                                                  int M, int N, int K) {
    extern __shared__ float smf[];
    const uint32_t sbase = (uint32_t)__cvta_generic_to_shared(smf);

    const int tid  = threadIdx.x;
    const int lane = tid & 31;
    const int w    = tid >> 5;
    const int wm   = w >> 2, wn = w & 3;
    const int g    = lane >> 2, t = lane & 3;

    const int row0 = blockIdx.y * 128;
    const int col0 = blockIdx.x * 128;
    const int niter = K >> 5;

    float acc[4][4][4];
#pragma unroll
    for (int i = 0; i < 4; i++)
#pragma unroll
        for (int j = 0; j < 4; j++)
#pragma unroll
            for (int r = 0; r < 4; r++) acc[i][j][r] = 0.f;

    auto issue = [&](int it) {
        if (it < niter) {
            const int k0 = it << 5;
            const uint32_t ab = sbase + (uint32_t)(it % 3) * 32768u;
#pragma unroll
            for (int l = 0; l < 4; l++) {
                int c   = tid + (l << 8);
                int row = c >> 3;
                int k4  = (c & 7) << 2;
                uint32_t sw = (uint32_t)((row * 32 + (k4 ^ ((row & 7) << 2))) << 2);
                int ar = row0 + row;
                cp16(ab + sw, A + (size_t)(ar < M ? ar : M - 1) * K + k0 + k4, ar < M);
                cp16(ab + 16384u + sw, Bm + (size_t)(col0 + row) * K + k0 + k4, true);
            }
        }
        CP_COMMIT();
    };

    issue(0);
    issue(1);

    uint32_t baseA[4], baseB[2];
#pragma unroll
    for (int i = 0; i < 4; i++) {
        int row = wm * 64 + i * 16 + (lane & 15);
        int kg  = lane >> 4;
        baseA[i] = (uint32_t)((row * 32 + ((kg * 4) ^ ((row & 7) << 2))) << 2);
    }
#pragma unroll
    for (int u = 0; u < 2; u++) {
        int n  = wn * 32 + u * 16 + ((lane >> 4) << 3) + (lane & 7);
        int kg = (lane >> 3) & 1;
        baseB[u] = 16384u + (uint32_t)((n * 32 + ((kg * 4) ^ ((n & 7) << 2))) << 2);
    }

    for (int it = 0; it < niter; it++) {
        CP_WAIT(1);
        __syncthreads();
        issue(it + 2);

        const uint32_t stage = sbase + (uint32_t)(it % 3) * 32768u;
#pragma unroll
        for (int ks = 0; ks < 4; ks++) {
            const uint32_t kx = (uint32_t)(ks << 5);
            uint4 a[4], bb2[2];
#pragma unroll
            for (int i = 0; i < 4; i++) ldsm4(a[i], stage + (baseA[i] ^ kx));
#pragma unroll
            for (int u = 0; u < 2; u++) ldsm4(bb2[u], stage + (baseB[u] ^ kx));
            uint2 b[4];
            b[0] = make_uint2(bb2[0].x, bb2[0].y);
            b[1] = make_uint2(bb2[0].z, bb2[0].w);
            b[2] = make_uint2(bb2[1].x, bb2[1].y);
            b[3] = make_uint2(bb2[1].z, bb2[1].w);
#pragma unroll
            for (int i = 0; i < 4; i++)
#pragma unroll
                for (int j = 0; j < 4; j++)
                    mma_tf32(acc[i][j], a[i], b[j]);
        }
    }

#pragma unroll
    for (int i = 0; i < 4; i++) {
        int r_up = row0 + wm * 64 + i * 16 + g;
        int r_lo = r_up + 8;
#pragma unroll
        for (int j = 0; j < 4; j++) {
            int c = col0 + wn * 32 + j * 8 + t * 2;
            float bx = 0.f, by = 0.f;
            if (ADD_BIAS) { bx = bias[c]; by = bias[c + 1]; }
            float v0 = acc[i][j][0] + bx, v1 = acc[i][j][1] + by;
            float v2 = acc[i][j][2] + bx, v3 = acc[i][j][3] + by;
            if (CVT_OUT) {
                v0 = __uint_as_float(f2tf32(v0));
                v1 = __uint_as_float(f2tf32(v1));
                v2 = __uint_as_float(f2tf32(v2));
                v3 = __uint_as_float(f2tf32(v3));
            }
            if (r_up < M)
                *reinterpret_cast<float2*>(C + (size_t)r_up * N + c) = make_float2(v0, v1);
            if (r_lo < M)
                *reinterpret_cast<float2*>(C + (size_t)r_lo * N + c) = make_float2(v2, v3);
        }
    }
}

// ---------------------------------------------------------------------------
// Flash attention v3. 256 thr = 8 warps, 128 query rows/CTA, grid (5, 8, 32).
// Q fragments hoisted to registers; K token-major + V d-major (transposed via
// 4B cp.async gather) so BOTH S and PV loops are pure ldmatrix + mma.
// Smem words: Qs[8192] Pf[8192] | stage0: K[4096] V[4096] | stage1: K V
// ---------------------------------------------------------------------------
#define ATTN_SMEM_BYTES 131072

__global__ void __launch_bounds__(256) attn_cp_kernel() {
    extern __shared__ float smf[];
    const uint32_t sbase = (uint32_t)__cvta_generic_to_shared(smf);
    unsigned* Pf = reinterpret_cast<unsigned*>(smf) + 8192;

    const int tid  = threadIdx.x;
    const int lane = tid & 31;
    const int w    = tid >> 5;
    const int g    = lane >> 2;
    const int t    = lane & 3;

    const int b    = blockIdx.z;
    const int h    = blockIdx.y;
    const int row0 = blockIdx.x * 128;

    const float* base = g_qkv + (size_t)b * NTOK * QKVW + h * HD;
    const float* qb = base;
    const float* kb = base + DIM_C;
    const float* vb = base + 2 * DIM_C;
    const float* bb = g_bias + (size_t)h * NTOK * BSTR;

    // ---- Q tile via cp.async (row-major swizzled) ----
#pragma unroll
    for (int l = 0; l < 8; l++) {
        int c   = tid + (l << 8);
        int row = c >> 4;                 // 0..127
        int d4  = (c & 15) << 2;
        int gr  = row0 + row;
        uint32_t sw = (uint32_t)((row * 64 + (d4 ^ ((row & 7) << 2))) << 2);
        cp16(sbase + sw, qb + (size_t)(gr < NTOK ? gr : 0) * QKVW + d4, gr < NTOK);
    }

    auto issueKV = [&](int jt) {
        if (jt < 10) {
            int c0 = jt * 64;
            uint32_t ab = sbase + 65536u + (uint32_t)(jt & 1) * 32768u;
            // K: token-major rows (16B chunks)
#pragma unroll
            for (int l = 0; l < 4; l++) {
                int c   = tid + (l << 8);
                int row = c >> 4;         // token 0..63
                int d4  = (c & 15) << 2;
                int gc  = c0 + row;
                bool v  = gc < NTOK;
                uint32_t swK = (uint32_t)((row * 64 + (d4 ^ ((row & 7) << 2))) << 2);
                cp16(ab + swK, kb + (size_t)(v ? gc : 0) * QKVW + d4, v);
            }
            // V: transposed (d-major) via 4B gather; swizzle tok ^ ((d&7)<<2)
#pragma unroll
            for (int l = 0; l < 16; l++) {
                int c   = tid + (l << 8);
                int tok = c >> 6;         // 0..63
                int d   = c & 63;
                int gc  = c0 + tok;
                bool v  = gc < NTOK;
                uint32_t swV = (uint32_t)((d * 64 + (tok ^ ((d & 7) << 2))) << 2);
                cp4(ab + 16384u + swV, vb + (size_t)(v ? gc : 0) * QKVW + d, v);
            }
        }
        CP_COMMIT();
    };

    issueKV(0);   // group contains Q + first KV stage

    // ldmatrix base offsets
    uint32_t baseQ, baseK[4], baseV[4];
    {
        int row = w * 16 + (lane & 15);
        int kg  = lane >> 4;
        baseQ = (uint32_t)((row * 64 + ((kg * 4) ^ ((row & 7) << 2))) << 2);
    }
#pragma unroll
    for (int j = 0; j < 4; j++) {
        int n  = j * 16 + ((lane >> 4) << 3) + (lane & 7);
        int kg = (lane >> 3) & 1;
        baseK[j] = (uint32_t)((n * 64 + ((kg * 4) ^ ((n & 7) << 2))) << 2);
        baseV[j] = 16384u + (uint32_t)((n * 64 + ((kg * 4) ^ ((n & 7) << 2))) << 2);
    }

    float m0 = -1e30f, m1 = -1e30f, l0 = 0.f, l1 = 0.f;
    float O[8][4];
#pragma unroll
    for (int nt = 0; nt < 8; nt++)
#pragma unroll
        for (int r = 0; r < 4; r++) O[nt][r] = 0.f;

    uint4 aq[8];   // Q fragments, loop-invariant

    const int r_up = row0 + w * 16 + g;
    const int r_lo = r_up + 8;
    const float* b0p = bb + (size_t)(r_up < NTOK ? r_up : NTOK - 1) * BSTR;
    const float* b1p = bb + (size_t)(r_lo < NTOK ? r_lo : NTOK - 1) * BSTR;
    const float scale = 0.125f * LOG2E;

    for (int jt = 0; jt < 10; jt++) {
        const int col0 = jt * 64;
        CP_WAIT(0);
        __syncthreads();
        if (jt == 0) {
            // hoist Q fragments once (Q landed with group 0)
#pragma unroll
            for (int ks = 0; ks < 8; ks++)
                ldsm4(aq[ks], sbase + (baseQ ^ (uint32_t)(ks << 5)));
        }
        issueKV(jt + 1);

        const uint32_t kvb = sbase + 65536u + (uint32_t)(jt & 1) * 32768u;

        // ---- S = Q K^T (warp: 16 x 64) ----
        float S[8][4];
#pragma unroll
        for (int nt = 0; nt < 8; nt++)
#pragma unroll
            for (int r = 0; r < 4; r++) S[nt][r] = 0.f;
#pragma unroll
        for (int ks = 0; ks < 8; ks++) {
            const uint32_t kx = (uint32_t)(ks << 5);
#pragma unroll
            for (int j = 0; j < 4; j++) {
                uint4 kf;
                ldsm4(kf, kvb + (baseK[j] ^ kx));
                mma_tf32(S[2 * j],     aq[ks], make_uint2(kf.x, kf.y));
                mma_tf32(S[2 * j + 1], aq[ks], make_uint2(kf.z, kf.w));
            }
        }

        // ---- scale + bias (log2 domain, 8B-aligned float2 loads) + mask ----
#pragma unroll
        for (int nt = 0; nt < 8; nt++) {
            int c = col0 + nt * 8 + t * 2;
            bool v0 = (c < NTOK), v1 = (c + 1 < NTOK);
            float2 bA = v0 ? *reinterpret_cast<const float2*>(b0p + c)
                           : make_float2(0.f, 0.f);
            float2 bB = v0 ? *reinterpret_cast<const float2*>(b1p + c)
                           : make_float2(0.f, 0.f);
            S[nt][0] = v0 ? fmaf(S[nt][0], scale, bA.x) : -1e30f;
            S[nt][1] = v1 ? fmaf(S[nt][1], scale, bA.y) : -1e30f;
            S[nt][2] = v0 ? fmaf(S[nt][2], scale, bB.x) : -1e30f;
            S[nt][3] = v1 ? fmaf(S[nt][3], scale, bB.y) : -1e30f;
        }

        // ---- online softmax in exp2 domain (rows spread over 4 lanes) ----
        float mx0 = -1e30f, mx1 = -1e30f;
#pragma unroll
        for (int nt = 0; nt < 8; nt++) {
            mx0 = fmaxf(mx0, fmaxf(S[nt][0], S[nt][1]));
            mx1 = fmaxf(mx1, fmaxf(S[nt][2], S[nt][3]));
        }
#pragma unroll
        for (int off = 1; off < 4; off <<= 1) {
            mx0 = fmaxf(mx0, __shfl_xor_sync(0xffffffffu, mx0, off));
            mx1 = fmaxf(mx1, __shfl_xor_sync(0xffffffffu, mx1, off));
        }
        float mn0 = fmaxf(m0, mx0), mn1 = fmaxf(m1, mx1);
        float a0 = exp2f(m0 - mn0), a1 = exp2f(m1 - mn1);
        float s0 = 0.f, s1 = 0.f;
#pragma unroll
        for (int nt = 0; nt < 8; nt++) {
            S[nt][0] = exp2f(S[nt][0] - mn0);
            S[nt][1] = exp2f(S[nt][1] - mn0);
            S[nt][2] = exp2f(S[nt][2] - mn1);
            S[nt][3] = exp2f(S[nt][3] - mn1);
            s0 += S[nt][0] + S[nt][1];
            s1 += S[nt][2] + S[nt][3];
        }
#pragma unroll
        for (int off = 1; off < 4; off <<= 1) {
            s0 += __shfl_xor_sync(0xffffffffu, s0, off);
            s1 += __shfl_xor_sync(0xffffffffu, s1, off);
        }
        l0 = l0 * a0 + s0;  m0 = mn0;
        l1 = l1 * a1 + s1;  m1 = mn1;
#pragma unroll
        for (int nt = 0; nt < 8; nt++) {
            O[nt][0] *= a0; O[nt][1] *= a0;
            O[nt][2] *= a1; O[nt][3] *= a1;
        }

        // ---- P (D-frag) -> warp-private A-frag smem ----
#pragma unroll
        for (int nt = 0; nt < 8; nt++) {
            int cc = nt * 8 + t * 2;
            int kc0 = cc & 7, kc1 = (cc + 1) & 7;
            unsigned* pbase = &Pf[(w * 8 + nt) * 128];
            pbase[((g & 7) * 4 + (kc0 & 3)) * 4 + ((kc0 >> 2) << 1)]     = f2tf32(S[nt][0]);
            pbase[((g & 7) * 4 + (kc1 & 3)) * 4 + ((kc1 >> 2) << 1)]     = f2tf32(S[nt][1]);
            pbase[((g & 7) * 4 + (kc0 & 3)) * 4 + ((kc0 >> 2) << 1) + 1] = f2tf32(S[nt][2]);
            pbase[((g & 7) * 4 + (kc1 & 3)) * 4 + ((kc1 >> 2) << 1) + 1] = f2tf32(S[nt][3]);
        }
        __syncwarp();

        // ---- O += P @ V (V B-frags via ldmatrix on d-major tile) ----
#pragma unroll
        for (int ks = 0; ks < 8; ks++) {
            uint4 a = *reinterpret_cast<const uint4*>(&Pf[(w * 8 + ks) * 128 + lane * 4]);
            const uint32_t kx = (uint32_t)(ks << 5);
#pragma unroll
            for (int j = 0; j < 4; j++) {
                uint4 vf;
                ldsm4(vf, kvb + (baseV[j] ^ kx));
                mma_tf32(O[2 * j],     a, make_uint2(vf.x, vf.y));
                mma_tf32(O[2 * j + 1], a, make_uint2(vf.z, vf.w));
            }
        }
        __syncwarp();
    }

    // ---- epilogue (write tf32-rounded so out-proj needs no cvt) ----
    float inv0 = 1.0f / l0, inv1 = 1.0f / l1;
#pragma unroll
    for (int nt = 0; nt < 8; nt++) {
        int c = nt * 8 + t * 2;
        if (r_up < NTOK) {
            float2 v;
            v.x = __uint_as_float(f2tf32(O[nt][0] * inv0));
            v.y = __uint_as_float(f2tf32(O[nt][1] * inv0));
            *reinterpret_cast<float2*>(
                g_att + ((size_t)b * NTOK + r_up) * DIM_C + h * HD + c) = v;
        }
        if (r_lo < NTOK) {
            float2 v;
            v.x = __uint_as_float(f2tf32(O[nt][2] * inv1));
            v.y = __uint_as_float(f2tf32(O[nt][3] * inv1));
            *reinterpret_cast<float2*>(
                g_att + ((size_t)b * NTOK + r_lo) * DIM_C + h * HD + c) = v;
        }
    }
}

// ---------------------------------------------------------------------------
// Launcher
// ---------------------------------------------------------------------------
#define GEMM_SMEM_BYTES 98304

extern "C" void kernel_launch(void* const* d_in, const int* in_sizes, int n_in,
                              void* d_out, int out_size) {
    const float* x      = (const float*)d_in[0];
    const float* qkv_w  = (const float*)d_in[1];
    const float* proj_w = (const float*)d_in[2];
    const float* proj_b = (const float*)d_in[3];
    const float* table  = (const float*)d_in[4];
    const int*   rel    = (const int*)d_in[5];
    float*       out    = (float*)d_out;

    void *qkv_p = nullptr, *att_p = nullptr, *xr_p = nullptr, *wq_p = nullptr, *wp_p = nullptr;
    cudaGetSymbolAddress(&qkv_p, g_qkv);
    cudaGetSymbolAddress(&att_p, g_att);
    cudaGetSymbolAddress(&xr_p,  g_xr);
    cudaGetSymbolAddress(&wq_p,  g_wqkv);
    cudaGetSymbolAddress(&wp_p,  g_wp);

    cudaFuncSetAttribute(gemm_cp<true, false>,
                         cudaFuncAttributeMaxDynamicSharedMemorySize, GEMM_SMEM_BYTES);
    cudaFuncSetAttribute(gemm_cp<false, true>,
                         cudaFuncAttributeMaxDynamicSharedMemorySize, GEMM_SMEM_BYTES);
    cudaFuncSetAttribute(attn_cp_kernel,
                         cudaFuncAttributeMaxDynamicSharedMemorySize, ATTN_SMEM_BYTES);

    // 0) pre-round inputs to tf32 values
    round_kernel<<<(MROWS * DIM_C / 4 + 255) / 256, 256>>>(x, (float*)xr_p, MROWS * DIM_C / 4);
    round_kernel<<<(QKVW * DIM_C / 4 + 255) / 256, 256>>>(qkv_w, (float*)wq_p, QKVW * DIM_C / 4);
    round_kernel<<<(DIM_C * DIM_C / 4 + 255) / 256, 256>>>(proj_w, (float*)wp_p, DIM_C * DIM_C / 4);

    // 1) bias materialization (padded stride, pre-scaled by log2e)
    bias_kernel<<<(NN + 255) / 256, 256>>>(table, rel);

    // 2) QKV projection (rounds outputs)
    gemm_cp<true, false><<<dim3(QKVW / 128, (MROWS + 127) / 128), 256, GEMM_SMEM_BYTES>>>(
        (const float*)xr_p, (const float*)wq_p, nullptr, (float*)qkv_p, MROWS, QKVW, DIM_C);

    // 3) attention (writes rounded g_att)
    attn_cp_kernel<<<dim3(5, HEADS, B_SZ), 256, ATTN_SMEM_BYTES>>>();

    // 4) output projection + bias -> d_out (full f32 out)
    gemm_cp<false, true><<<dim3(DIM_C / 128, (MROWS + 127) / 128), 256, GEMM_SMEM_BYTES>>>(
        (const float*)att_p, (const float*)wp_p, proj_b, out, MROWS, DIM_C, DIM_C);
}